// round 12
// baseline (speedup 1.0000x reference)
#include <cuda_runtime.h>
#include <cuda_fp16.h>
#include <math.h>
#include <stdint.h>

// Problem constants
#define BB 32
#define TT 2048
#define HH 1024
#define UU 1024
#define KN 32
#define KSZ 15
#define KW 31
#define KAUG (HH + KN)   // 1056
#define KP 1088          // padded K (17 * 64); [1056,1088) zeros
#define BK 64            // K per chunk (fp16) = 128 bytes per row
#define NCHUNK (KP / BK) // 17
#define NSTAGE 3

#define BM 128
#define BN 128

// Output layout in d_out (float):
#define OUT_CTX 0
#define OUT_ATT (BB * HH)
#define OUT_SCORE (BB * HH + BB * TT)

// Scratch (device globals)
__device__ float g_locT[BB * TT * KN];
__device__ float g_dbias[BB * UU];
__device__ __half g_Ah[(size_t)BB * TT * KP];   // fp16(values | locT | 0pad)
__device__ __half g_Wh[(size_t)UU * KP];        // fp16(W1_w | loc_proj_w | 0pad)

// ---------------------------------------------------------------------------
__device__ __forceinline__ uint32_t smem_u32(const void* p) {
    uint32_t a;
    asm("{ .reg .u64 t; cvta.to.shared.u64 t, %1; cvt.u32.u64 %0, t; }"
        : "=r"(a) : "l"(p));
    return a;
}

__device__ __forceinline__ void cp16(uint32_t saddr, const void* gaddr) {
    asm volatile("cp.async.cg.shared.global [%0], [%1], 16;"
                 :: "r"(saddr), "l"(gaddr));
}
#define CP_COMMIT() asm volatile("cp.async.commit_group;" ::: "memory")
#define CP_WAIT2()  asm volatile("cp.async.wait_group 2;" ::: "memory")

__device__ __forceinline__ void ldm_x4(uint32_t* r, uint32_t addr) {
    asm volatile("ldmatrix.sync.aligned.m8n8.x4.shared.b16 {%0,%1,%2,%3}, [%4];"
                 : "=r"(r[0]), "=r"(r[1]), "=r"(r[2]), "=r"(r[3]) : "r"(addr));
}

__device__ __forceinline__ void mma16816(float* d, const uint32_t* a,
                                         uint32_t b0, uint32_t b1) {
    asm volatile(
        "mma.sync.aligned.m16n8k16.row.col.f32.f16.f16.f32 "
        "{%0,%1,%2,%3}, {%4,%5,%6,%7}, {%8,%9}, {%0,%1,%2,%3};"
        : "+f"(d[0]), "+f"(d[1]), "+f"(d[2]), "+f"(d[3])
        : "r"(a[0]), "r"(a[1]), "r"(a[2]), "r"(a[3]), "r"(b0), "r"(b1));
}

// swizzle for 128-byte rows: XOR bits[6:4] with row bits[2:0]
__device__ __forceinline__ uint32_t swz(int row, int inrow) {
    return (uint32_t)(row * 128 + (inrow ^ ((row & 7) << 4)));
}

// ---------------------------------------------------------------------------
// 1) Conv1d over prev_att -> locT[b][t][k]
// ---------------------------------------------------------------------------
__global__ void conv_kernel(const float* __restrict__ prev,
                            const float* __restrict__ convw) {
    int b = blockIdx.x / KN;
    int k = blockIdx.x % KN;
    __shared__ float w[KW];
    if (threadIdx.x < KW) w[threadIdx.x] = convw[k * KW + threadIdx.x];
    __syncthreads();
    const float* pb = prev + b * TT;
    for (int t = threadIdx.x; t < TT; t += blockDim.x) {
        float acc = 0.f;
#pragma unroll
        for (int j = 0; j < KW; j++) {
            int tt = t + j - KSZ;
            float p = (tt >= 0 && tt < TT) ? pb[tt] : 0.f;
            acc = fmaf(p, w[j], acc);
        }
        g_locT[((size_t)b * TT + t) * KN + k] = acc;
    }
}

// ---------------------------------------------------------------------------
// 2) Per-(b,u) bias
// ---------------------------------------------------------------------------
__global__ void dbias_kernel(const float* __restrict__ q,
                             const float* __restrict__ W2w,
                             const float* __restrict__ W1b,
                             const float* __restrict__ W2b) {
    int warp = threadIdx.x >> 5;
    int lane = threadIdx.x & 31;
    int u = blockIdx.x * 8 + warp;
    float w2[32];
#pragma unroll
    for (int i = 0; i < 32; i++) w2[i] = W2w[(size_t)u * HH + lane + 32 * i];
    float bias = W1b[u] + W2b[u];
    for (int b = 0; b < BB; b++) {
        float p = 0.f;
        const float* qb = q + (size_t)b * HH;
#pragma unroll
        for (int i = 0; i < 32; i++) p = fmaf(w2[i], qb[lane + 32 * i], p);
#pragma unroll
        for (int off = 16; off; off >>= 1) p += __shfl_xor_sync(0xFFFFFFFFu, p, off);
        if (lane == 0) g_dbias[b * UU + u] = p + bias;
    }
}

// ---------------------------------------------------------------------------
// 3a) values|locT -> fp16, vectorized (K = 1024 + 32 + 32 zeros)
// ---------------------------------------------------------------------------
__global__ void convertA_kernel(const float* __restrict__ values) {
    size_t row = blockIdx.x;
    const float4* vrow = (const float4*)(values + row * HH);
    __half* ah = g_Ah + row * KP;
    int t = (int)threadIdx.x;   // 0..255
    {
        float4 v = vrow[t];
        __half2* o = (__half2*)(ah + t * 4);
        o[0] = __floats2half2_rn(v.x, v.y);
        o[1] = __floats2half2_rn(v.z, v.w);
    }
    if (t < 8) {
        const float4* lrow = (const float4*)(g_locT + row * KN);
        float4 v = lrow[t];
        __half2* o = (__half2*)(ah + HH + t * 4);
        o[0] = __floats2half2_rn(v.x, v.y);
        o[1] = __floats2half2_rn(v.z, v.w);
    } else if (t < 16) {
        // zero pad [1056, 1088)
        __half2* o = (__half2*)(ah + KAUG + (t - 8) * 4);
        o[0] = __half2half2(__float2half_rn(0.f));
        o[1] = __half2half2(__float2half_rn(0.f));
    }
}

// ---------------------------------------------------------------------------
// 3b) [W1_w | loc_proj_w | 0pad] -> fp16
// ---------------------------------------------------------------------------
__global__ void convertW_kernel(const float* __restrict__ W1w,
                                const float* __restrict__ locpw) {
    size_t u = blockIdx.x;
    const float* w1 = W1w + u * HH;
    const float* lp = locpw + u * KN;
    __half* wh = g_Wh + u * KP;
    for (int k = threadIdx.x; k < KP; k += blockDim.x) {
        float a = (k < HH) ? w1[k] : (k < KAUG ? lp[k - HH] : 0.f);
        wh[k] = __float2half_rn(a);
    }
}

__global__ void init_out_kernel(const float* __restrict__ Vb, float* __restrict__ out) {
    int stride = gridDim.x * blockDim.x;
    int tid0 = blockIdx.x * blockDim.x + threadIdx.x;
    float vb = Vb[0];
    for (int i = tid0; i < BB * TT; i += stride) out[OUT_SCORE + i] = vb;
    for (int i = tid0; i < BB * HH; i += stride) out[OUT_CTX + i] = 0.f;
}

// ---------------------------------------------------------------------------
// 4) HMMA fp16 score GEMM, fused tanh + V_w epilogue
//    CTA 128x128, 8 warps (4m x 2n), BK=64, 3-stage cp.async (R8 loop order)
// ---------------------------------------------------------------------------
#define STG_A 0
#define STG_B 16384
#define STG_SZ 32768
#define SM_RED (NSTAGE * STG_SZ)                 // 98304
#define SMEM_GEMM_BYTES (NSTAGE * STG_SZ + BM * 8 * 4)   // 102400

__global__ void __launch_bounds__(256, 2)
score_gemm_tc(const float* __restrict__ Vw, float* __restrict__ out) {
    extern __shared__ char smem[];
    uint32_t sb = smem_u32(smem);

    int tid = (int)threadIdx.x;
    int lane = tid & 31;
    int wid = tid >> 5;
    int warp_m = wid >> 1;   // 0..3
    int warp_n = wid & 1;    // 0..1
    int b = blockIdx.z;
    int tTile = blockIdx.x;
    int uTile = blockIdx.y;

    size_t aRow0 = (size_t)b * TT + tTile * BM;
    size_t uRow0 = (size_t)uTile * BN;

    // per-thread load slots: 4 x 16B per array per chunk (128 rows x 8 slots)
    uint32_t swoff[4];
    size_t gbA[4], gbB[4];
#pragma unroll
    for (int r = 0; r < 4; r++) {
        int id = tid * 4 + r;
        int row = id >> 3, sl = id & 7;
        swoff[r] = swz(row, sl * 16);
        gbA[r] = ((aRow0 + row) * KP + sl * 8) * 2;   // bytes
        gbB[r] = ((uRow0 + row) * KP + sl * 8) * 2;
    }

    const char* pA = (const char*)g_Ah;
    const char* pW = (const char*)g_Wh;

    // prologue: stages 0..2
#pragma unroll
    for (int c = 0; c < NSTAGE; c++) {
        uint32_t s0 = sb + c * STG_SZ;
        size_t gk = (size_t)c * BK * 2;
#pragma unroll
        for (int r = 0; r < 4; r++) {
            cp16(s0 + STG_A + swoff[r], pA + gbA[r] + gk);
            cp16(s0 + STG_B + swoff[r], pW + gbB[r] + gk);
        }
        CP_COMMIT();
    }

    float acc[2][8][4];
#pragma unroll
    for (int mt = 0; mt < 2; mt++)
#pragma unroll
        for (int nt = 0; nt < 8; nt++)
#pragma unroll
            for (int i = 0; i < 4; i++) acc[mt][nt][i] = 0.f;

    for (int c = 0; c < NCHUNK; c++) {
        CP_WAIT2();
        __syncthreads();
        uint32_t s0;
        {
            int slot = c % NSTAGE;
            s0 = sb + slot * STG_SZ;
        }

#pragma unroll
        for (int ks = 0; ks < 4; ks++) {
            uint32_t ah[8];
#pragma unroll
            for (int mt = 0; mt < 2; mt++) {
                int row = warp_m * 32 + mt * 16 + (lane & 15);
                uint32_t off = swz(row, ks * 32 + (lane >> 4) * 16);
                ldm_x4(ah + mt * 4, s0 + STG_A + off);
            }
            uint32_t bb[16];
#pragma unroll
            for (int p = 0; p < 4; p++) {
                int t = lane >> 3;
                int n = warp_n * 64 + p * 16 + ((t & 2) ? 8 : 0) + (lane & 7);
                int koff = ks * 32 + ((t & 1) ? 16 : 0);
                ldm_x4(bb + p * 4, s0 + STG_B + swz(n, koff));
            }
#pragma unroll
            for (int p = 0; p < 4; p++) {
                mma16816(acc[0][2 * p],     ah,     bb[4 * p + 0], bb[4 * p + 1]);
                mma16816(acc[1][2 * p],     ah + 4, bb[4 * p + 0], bb[4 * p + 1]);
                mma16816(acc[0][2 * p + 1], ah,     bb[4 * p + 2], bb[4 * p + 3]);
                mma16816(acc[1][2 * p + 1], ah + 4, bb[4 * p + 2], bb[4 * p + 3]);
            }
        }
        __syncthreads();
        int cn = c + NSTAGE;
        if (cn < NCHUNK) {
            size_t gk = (size_t)cn * BK * 2;
#pragma unroll
            for (int r = 0; r < 4; r++) {
                cp16(s0 + STG_A + swoff[r], pA + gbA[r] + gk);
                cp16(s0 + STG_B + swoff[r], pW + gbB[r] + gk);
            }
        }
        CP_COMMIT();
    }

    // Epilogue: tanh + V_w dot, reduce 8 partials per row
    const float* db = g_dbias + b * UU + uTile * BN + warp_n * 64;
    const float* vw = Vw + uTile * BN + warp_n * 64;
    float p[2][2] = {{0.f, 0.f}, {0.f, 0.f}};
#pragma unroll
    for (int mt = 0; mt < 2; mt++)
#pragma unroll
        for (int nt = 0; nt < 8; nt++) {
            int u0 = nt * 8 + (lane & 3) * 2;
            float d0 = db[u0], d1 = db[u0 + 1];
            float v0 = vw[u0], v1 = vw[u0 + 1];
            p[mt][0] += tanhf(acc[mt][nt][0] + d0) * v0
                      + tanhf(acc[mt][nt][1] + d1) * v1;
            p[mt][1] += tanhf(acc[mt][nt][2] + d0) * v0
                      + tanhf(acc[mt][nt][3] + d1) * v1;
        }
    float* red = (float*)(smem + SM_RED);
#pragma unroll
    for (int mt = 0; mt < 2; mt++)
#pragma unroll
        for (int half = 0; half < 2; half++) {
            int row = warp_m * 32 + mt * 16 + half * 8 + (lane >> 2);
            red[row * 8 + warp_n * 4 + (lane & 3)] = p[mt][half];
        }
    __syncthreads();
    if (tid < BM) {
        const float* rr = red + tid * 8;
        float s = 0.f;
#pragma unroll
        for (int j = 0; j < 8; j++) s += rr[j];
        atomicAdd(&out[OUT_SCORE + b * TT + tTile * BM + tid], s);
    }
}

// ---------------------------------------------------------------------------
// 5) Softmax over t per batch
// ---------------------------------------------------------------------------
__global__ void softmax_kernel(float* __restrict__ out) {
    int b = blockIdx.x;
    const float* sc = out + OUT_SCORE + b * TT;
    float* att = out + OUT_ATT + b * TT;
    __shared__ float sred[256];
    int tid = (int)threadIdx.x;
    float v[8];
    float m = -1e30f;
#pragma unroll
    for (int i = 0; i < 8; i++) {
        v[i] = sc[tid + 256 * i];
        m = fmaxf(m, v[i]);
    }
    sred[tid] = m;
    __syncthreads();
    for (int s = 128; s; s >>= 1) {
        if (tid < s) sred[tid] = fmaxf(sred[tid], sred[tid + s]);
        __syncthreads();
    }
    m = sred[0];
    __syncthreads();
    float sum = 0.f;
#pragma unroll
    for (int i = 0; i < 8; i++) {
        v[i] = expf(v[i] - m);
        sum += v[i];
    }
    sred[tid] = sum;
    __syncthreads();
    for (int s = 128; s; s >>= 1) {
        if (tid < s) sred[tid] += sred[tid + s];
        __syncthreads();
    }
    float inv = 1.f / sred[0];
#pragma unroll
    for (int i = 0; i < 8; i++) att[tid + 256 * i] = v[i] * inv;
}

// ---------------------------------------------------------------------------
// 6) context[b,h] = sum_t att[b,t] * Ah[b,t,h]  (fp16 values, half traffic)
// ---------------------------------------------------------------------------
__global__ void context_kernel(float* __restrict__ out) {
    int b = blockIdx.z;
    int h = blockIdx.x * 128 + (int)threadIdx.x;
    int t0 = blockIdx.y * 128;
    const float* att = out + OUT_ATT + b * TT;
    const __half* vp = g_Ah + ((size_t)b * TT + t0) * KP + h;
    float acc = 0.f;
#pragma unroll 8
    for (int t = 0; t < 128; t++) {
        acc = fmaf(att[t0 + t], __half2float(vp[(size_t)t * KP]), acc);
    }
    atomicAdd(&out[OUT_CTX + b * HH + h], acc);
}

// ---------------------------------------------------------------------------
extern "C" void kernel_launch(void* const* d_in, const int* in_sizes, int n_in,
                              void* d_out, int out_size) {
    const float* query   = (const float*)d_in[0];
    const float* values  = (const float*)d_in[1];
    const float* prev    = (const float*)d_in[2];
    const float* W1w     = (const float*)d_in[3];
    const float* W1b     = (const float*)d_in[4];
    const float* W2w     = (const float*)d_in[5];
    const float* W2b     = (const float*)d_in[6];
    const float* Vw      = (const float*)d_in[7];
    const float* Vb      = (const float*)d_in[8];
    const float* convw   = (const float*)d_in[9];
    const float* locpw   = (const float*)d_in[10];
    float* out = (float*)d_out;

    cudaFuncSetAttribute(score_gemm_tc,
                         cudaFuncAttributeMaxDynamicSharedMemorySize,
                         SMEM_GEMM_BYTES);

    conv_kernel<<<BB * KN, 256>>>(prev, convw);
    dbias_kernel<<<UU / 8, 256>>>(query, W2w, W1b, W2b);
    convertA_kernel<<<BB * TT, 256>>>(values);
    convertW_kernel<<<UU, 256>>>(W1w, locpw);
    init_out_kernel<<<256, 256>>>(Vb, out);
    score_gemm_tc<<<dim3(TT / BM, UU / BN, BB), 256, SMEM_GEMM_BYTES>>>(Vw, out);
    softmax_kernel<<<BB, 256>>>(out);
    context_kernel<<<dim3(HH / 128, TT / 128, BB), 128>>>(out);
}

// round 13
// speedup vs baseline: 1.0787x; 1.0787x over previous
#include <cuda_runtime.h>
#include <cuda_fp16.h>
#include <math.h>
#include <stdint.h>

// Problem constants
#define BB 32
#define TT 2048
#define HH 1024
#define UU 1024
#define KN 32
#define KSZ 15
#define KW 31
#define KAUG (HH + KN)   // 1056
#define KP 1056          // K (33 * 32 exactly)
#define BK 32            // K per chunk (fp16) = 64 bytes per row
#define NCHUNK (KP / BK) // 33
#define NSTAGE 6

#define BM 128
#define BN 128

// Output layout in d_out (float):
#define OUT_CTX 0
#define OUT_ATT (BB * HH)
#define OUT_SCORE (BB * HH + BB * TT)

// Scratch (device globals)
__device__ float g_dbias[BB * UU];
__device__ __half g_Ah[(size_t)BB * TT * KP];   // fp16(values | loc)
__device__ __half g_Wh[(size_t)UU * KP];        // fp16(W1_w | loc_proj_w)

// ---------------------------------------------------------------------------
__device__ __forceinline__ uint32_t smem_u32(const void* p) {
    uint32_t a;
    asm("{ .reg .u64 t; cvta.to.shared.u64 t, %1; cvt.u32.u64 %0, t; }"
        : "=r"(a) : "l"(p));
    return a;
}

__device__ __forceinline__ void cp16(uint32_t saddr, const void* gaddr) {
    asm volatile("cp.async.cg.shared.global [%0], [%1], 16;"
                 :: "r"(saddr), "l"(gaddr));
}
#define CP_COMMIT() asm volatile("cp.async.commit_group;" ::: "memory")
#define CP_WAIT5()  asm volatile("cp.async.wait_group 5;" ::: "memory")

__device__ __forceinline__ void ldm_x4(uint32_t* r, uint32_t addr) {
    asm volatile("ldmatrix.sync.aligned.m8n8.x4.shared.b16 {%0,%1,%2,%3}, [%4];"
                 : "=r"(r[0]), "=r"(r[1]), "=r"(r[2]), "=r"(r[3]) : "r"(addr));
}

__device__ __forceinline__ void mma16816(float* d, const uint32_t* a,
                                         uint32_t b0, uint32_t b1) {
    asm volatile(
        "mma.sync.aligned.m16n8k16.row.col.f32.f16.f16.f32 "
        "{%0,%1,%2,%3}, {%4,%5,%6,%7}, {%8,%9}, {%0,%1,%2,%3};"
        : "+f"(d[0]), "+f"(d[1]), "+f"(d[2]), "+f"(d[3])
        : "r"(a[0]), "r"(a[1]), "r"(a[2]), "r"(a[3]), "r"(b0), "r"(b1));
}

__device__ __forceinline__ float tanh_fast(float x) {
    float y;
    asm("tanh.approx.f32 %0, %1;" : "=f"(y) : "f"(x));
    return y;
}

// swizzle: 64B rows, XOR bits[5:4] with row bits[2:1] -> conflict-free ldmatrix
__device__ __forceinline__ uint32_t swz(int row, int inrow) {
    return (uint32_t)(row * 64 + (inrow ^ ((row & 6) << 3)));
}

// ---------------------------------------------------------------------------
// 1) Per-(b,u) bias
// ---------------------------------------------------------------------------
__global__ void dbias_kernel(const float* __restrict__ q,
                             const float* __restrict__ W2w,
                             const float* __restrict__ W1b,
                             const float* __restrict__ W2b) {
    int warp = threadIdx.x >> 5;
    int lane = threadIdx.x & 31;
    int u = blockIdx.x * 8 + warp;
    float w2[32];
#pragma unroll
    for (int i = 0; i < 32; i++) w2[i] = W2w[(size_t)u * HH + lane + 32 * i];
    float bias = W1b[u] + W2b[u];
    for (int b = 0; b < BB; b++) {
        float p = 0.f;
        const float* qb = q + (size_t)b * HH;
#pragma unroll
        for (int i = 0; i < 32; i++) p = fmaf(w2[i], qb[lane + 32 * i], p);
#pragma unroll
        for (int off = 16; off; off >>= 1) p += __shfl_xor_sync(0xFFFFFFFFu, p, off);
        if (lane == 0) g_dbias[b * UU + u] = p + bias;
    }
}

// ---------------------------------------------------------------------------
// 2) Fused conv + convert: row (b,t) -> g_Ah[row] = fp16(values[row] | loc)
// ---------------------------------------------------------------------------
__global__ void convertA_kernel(const float* __restrict__ values,
                                const float* __restrict__ prev,
                                const float* __restrict__ convw) {
    int row = (int)blockIdx.x;            // b * TT + t
    int b = row >> 11;                    // TT = 2048
    int t = row & (TT - 1);
    int tid = (int)threadIdx.x;
    __shared__ float loc[KN];

    if (tid < KN) {
        const float* pb = prev + b * TT;
        const float* w = convw + tid * KW;
        float acc = 0.f;
#pragma unroll
        for (int j = 0; j < KW; j++) {
            int tt = t + j - KSZ;
            float p = (tt >= 0 && tt < TT) ? pb[tt] : 0.f;
            acc = fmaf(p, w[j], acc);
        }
        loc[tid] = acc;
    }

    const float4* vrow = (const float4*)(values + (size_t)row * HH);
    __half* ah = g_Ah + (size_t)row * KP;
    {
        float4 v = vrow[tid];
        __half2* o = (__half2*)(ah + tid * 4);
        o[0] = __floats2half2_rn(v.x, v.y);
        o[1] = __floats2half2_rn(v.z, v.w);
    }
    __syncthreads();
    if (tid < 8) {
        const float4* lrow = (const float4*)loc;
        float4 v = lrow[tid];
        __half2* o = (__half2*)(ah + HH + tid * 4);
        o[0] = __floats2half2_rn(v.x, v.y);
        o[1] = __floats2half2_rn(v.z, v.w);
    }
}

// ---------------------------------------------------------------------------
// 3) [W1_w | loc_proj_w] -> fp16
// ---------------------------------------------------------------------------
__global__ void convertW_kernel(const float* __restrict__ W1w,
                                const float* __restrict__ locpw) {
    size_t u = blockIdx.x;
    const float* w1 = W1w + u * HH;
    const float* lp = locpw + u * KN;
    __half* wh = g_Wh + u * KP;
    for (int k = threadIdx.x; k < KP; k += blockDim.x) {
        float a = (k < HH) ? w1[k] : lp[k - HH];
        wh[k] = __float2half_rn(a);
    }
}

__global__ void init_out_kernel(const float* __restrict__ Vb, float* __restrict__ out) {
    int stride = gridDim.x * blockDim.x;
    int tid0 = blockIdx.x * blockDim.x + threadIdx.x;
    float vb = Vb[0];
    for (int i = tid0; i < BB * TT; i += stride) out[OUT_SCORE + i] = vb;
    for (int i = tid0; i < BB * HH; i += stride) out[OUT_CTX + i] = 0.f;
}

// ---------------------------------------------------------------------------
// 4) HMMA fp16 score GEMM, fused tanh + V_w epilogue
//    CTA 128x128, 8 warps (4m x 2n), BK=32, 6-stage cp.async (R8 loop order)
// ---------------------------------------------------------------------------
#define STG_A 0
#define STG_B 8192
#define STG_SZ 16384
#define SM_RED (NSTAGE * STG_SZ)                 // 98304
#define SMEM_GEMM_BYTES (NSTAGE * STG_SZ + BM * 8 * 4)   // 102400

__global__ void __launch_bounds__(256, 2)
score_gemm_tc(const float* __restrict__ Vw, float* __restrict__ out) {
    extern __shared__ char smem[];
    uint32_t sb = smem_u32(smem);

    int tid = (int)threadIdx.x;
    int lane = tid & 31;
    int wid = tid >> 5;
    int warp_m = wid >> 1;   // 0..3
    int warp_n = wid & 1;    // 0..1
    int b = blockIdx.z;
    int tTile = blockIdx.x;
    int uTile = blockIdx.y;

    size_t aRow0 = (size_t)b * TT + tTile * BM;
    size_t uRow0 = (size_t)uTile * BN;

    // per-thread load slots: 2 x 16B per array per chunk
    uint32_t swoff[2];
    size_t gbA[2], gbB[2];
#pragma unroll
    for (int r = 0; r < 2; r++) {
        int id = tid * 2 + r;
        int row = id >> 2;
        int sl = id & 3;
        swoff[r] = swz(row, sl * 16);
        gbA[r] = ((aRow0 + row) * KP + sl * 8) * 2;   // bytes
        gbB[r] = ((uRow0 + row) * KP + sl * 8) * 2;
    }

    const char* pA = (const char*)g_Ah;
    const char* pW = (const char*)g_Wh;

    // prologue: stages 0..5
#pragma unroll
    for (int c = 0; c < NSTAGE; c++) {
        uint32_t s0 = sb + c * STG_SZ;
        size_t gk = (size_t)c * BK * 2;
#pragma unroll
        for (int r = 0; r < 2; r++) {
            cp16(s0 + STG_A + swoff[r], pA + gbA[r] + gk);
            cp16(s0 + STG_B + swoff[r], pW + gbB[r] + gk);
        }
        CP_COMMIT();
    }

    float acc[2][8][4];
#pragma unroll
    for (int mt = 0; mt < 2; mt++)
#pragma unroll
        for (int nt = 0; nt < 8; nt++)
#pragma unroll
            for (int i = 0; i < 4; i++) acc[mt][nt][i] = 0.f;

    int slot = 0;
    for (int c = 0; c < NCHUNK; c++) {
        CP_WAIT5();
        __syncthreads();
        uint32_t s0 = sb + slot * STG_SZ;

#pragma unroll
        for (int ks = 0; ks < 2; ks++) {
            uint32_t ah[8];
#pragma unroll
            for (int mt = 0; mt < 2; mt++) {
                int row = warp_m * 32 + mt * 16 + (lane & 15);
                uint32_t off = swz(row, (ks * 2 + (lane >> 4)) * 16);
                ldm_x4(ah + mt * 4, s0 + STG_A + off);
            }
            uint32_t bb[16];
#pragma unroll
            for (int p = 0; p < 4; p++) {
                int t = lane >> 3;
                int n = warp_n * 64 + p * 16 + ((t & 2) ? 8 : 0) + (lane & 7);
                int koff = ks * 32 + ((t & 1) ? 16 : 0);
                ldm_x4(bb + p * 4, s0 + STG_B + swz(n, koff));
            }
#pragma unroll
            for (int p = 0; p < 4; p++) {
                mma16816(acc[0][2 * p],     ah,     bb[4 * p + 0], bb[4 * p + 1]);
                mma16816(acc[1][2 * p],     ah + 4, bb[4 * p + 0], bb[4 * p + 1]);
                mma16816(acc[0][2 * p + 1], ah,     bb[4 * p + 2], bb[4 * p + 3]);
                mma16816(acc[1][2 * p + 1], ah + 4, bb[4 * p + 2], bb[4 * p + 3]);
            }
        }
        __syncthreads();
        int cn = c + NSTAGE;
        if (cn < NCHUNK) {
            size_t gk = (size_t)cn * BK * 2;
#pragma unroll
            for (int r = 0; r < 2; r++) {
                cp16(s0 + STG_A + swoff[r], pA + gbA[r] + gk);
                cp16(s0 + STG_B + swoff[r], pW + gbB[r] + gk);
            }
        }
        CP_COMMIT();
        slot = (slot + 1 == NSTAGE) ? 0 : slot + 1;
    }

    // Epilogue: tanh + V_w dot, reduce 8 partials per row
    const float* db = g_dbias + b * UU + uTile * BN + warp_n * 64;
    const float* vw = Vw + uTile * BN + warp_n * 64;
    float p[2][2] = {{0.f, 0.f}, {0.f, 0.f}};
#pragma unroll
    for (int mt = 0; mt < 2; mt++)
#pragma unroll
        for (int nt = 0; nt < 8; nt++) {
            int u0 = nt * 8 + (lane & 3) * 2;
            float d0 = db[u0], d1 = db[u0 + 1];
            float v0 = vw[u0], v1 = vw[u0 + 1];
            p[mt][0] += tanh_fast(acc[mt][nt][0] + d0) * v0
                      + tanh_fast(acc[mt][nt][1] + d1) * v1;
            p[mt][1] += tanh_fast(acc[mt][nt][2] + d0) * v0
                      + tanh_fast(acc[mt][nt][3] + d1) * v1;
        }
    float* red = (float*)(smem + SM_RED);
#pragma unroll
    for (int mt = 0; mt < 2; mt++)
#pragma unroll
        for (int half = 0; half < 2; half++) {
            int row = warp_m * 32 + mt * 16 + half * 8 + (lane >> 2);
            red[row * 8 + warp_n * 4 + (lane & 3)] = p[mt][half];
        }
    __syncthreads();
    if (tid < BM) {
        const float* rr = red + tid * 8;
        float s = 0.f;
#pragma unroll
        for (int j = 0; j < 8; j++) s += rr[j];
        atomicAdd(&out[OUT_SCORE + b * TT + tTile * BM + tid], s);
    }
}

// ---------------------------------------------------------------------------
// 5) Softmax over t per batch
// ---------------------------------------------------------------------------
__global__ void softmax_kernel(float* __restrict__ out) {
    int b = blockIdx.x;
    const float* sc = out + OUT_SCORE + b * TT;
    float* att = out + OUT_ATT + b * TT;
    __shared__ float sred[256];
    int tid = (int)threadIdx.x;
    float v[8];
    float m = -1e30f;
#pragma unroll
    for (int i = 0; i < 8; i++) {
        v[i] = sc[tid + 256 * i];
        m = fmaxf(m, v[i]);
    }
    sred[tid] = m;
    __syncthreads();
    for (int s = 128; s; s >>= 1) {
        if (tid < s) sred[tid] = fmaxf(sred[tid], sred[tid + s]);
        __syncthreads();
    }
    m = sred[0];
    __syncthreads();
    float sum = 0.f;
#pragma unroll
    for (int i = 0; i < 8; i++) {
        v[i] = expf(v[i] - m);
        sum += v[i];
    }
    sred[tid] = sum;
    __syncthreads();
    for (int s = 128; s; s >>= 1) {
        if (tid < s) sred[tid] += sred[tid + s];
        __syncthreads();
    }
    float inv = 1.f / sred[0];
#pragma unroll
    for (int i = 0; i < 8; i++) att[tid + 256 * i] = v[i] * inv;
}

// ---------------------------------------------------------------------------
// 6) context[b,h] = sum_t att[b,t] * Ah[b,t,h]  (fp16 values, half traffic)
// ---------------------------------------------------------------------------
__global__ void context_kernel(float* __restrict__ out) {
    int b = blockIdx.z;
    int h = blockIdx.x * 128 + (int)threadIdx.x;
    int t0 = blockIdx.y * 128;
    const float* att = out + OUT_ATT + b * TT;
    const __half* vp = g_Ah + ((size_t)b * TT + t0) * KP + h;
    float acc = 0.f;
#pragma unroll 8
    for (int t = 0; t < 128; t++) {
        acc = fmaf(att[t0 + t], __half2float(vp[(size_t)t * KP]), acc);
    }
    atomicAdd(&out[OUT_CTX + b * HH + h], acc);
}

// ---------------------------------------------------------------------------
extern "C" void kernel_launch(void* const* d_in, const int* in_sizes, int n_in,
                              void* d_out, int out_size) {
    const float* query   = (const float*)d_in[0];
    const float* values  = (const float*)d_in[1];
    const float* prev    = (const float*)d_in[2];
    const float* W1w     = (const float*)d_in[3];
    const float* W1b     = (const float*)d_in[4];
    const float* W2w     = (const float*)d_in[5];
    const float* W2b     = (const float*)d_in[6];
    const float* Vw      = (const float*)d_in[7];
    const float* Vb      = (const float*)d_in[8];
    const float* convw   = (const float*)d_in[9];
    const float* locpw   = (const float*)d_in[10];
    float* out = (float*)d_out;

    cudaFuncSetAttribute(score_gemm_tc,
                         cudaFuncAttributeMaxDynamicSharedMemorySize,
                         SMEM_GEMM_BYTES);

    dbias_kernel<<<UU / 8, 256>>>(query, W2w, W1b, W2b);
    convertA_kernel<<<BB * TT, 256>>>(values, prev, convw);
    convertW_kernel<<<UU, 256>>>(W1w, locpw);
    init_out_kernel<<<256, 256>>>(Vb, out);
    score_gemm_tc<<<dim3(TT / BM, UU / BN, BB), 256, SMEM_GEMM_BYTES>>>(Vw, out);
    softmax_kernel<<<BB, 256>>>(out);
    context_kernel<<<dim3(HH / 128, TT / 128, BB), 128>>>(out);
}